// round 9
// baseline (speedup 1.0000x reference)
#include <cuda_runtime.h>

#define NACC 352          // 32 G + 320 M (before squares)
#define PI_F 3.14159265358979323846f
#define C6   (PI_F / 6.0f)
#define C4   (PI_F / 4.0f)

// scratch
__device__ float g_feat[2 * 2048 * NACC];   // [half][atom(orig)][feature]
__device__ int   g_sperm[2048];             // sorted row -> original atom
__device__ float g_spos[2048 * 3];          // positions in sorted order

__device__ __forceinline__ float fast_tanh(float x) {
    float y;
    asm("tanh.approx.f32 %0, %1;" : "=f"(y) : "f"(x));
    return y;
}
__device__ __forceinline__ float fast_sigmoid(float x) {
    return 0.5f * fast_tanh(0.5f * x) + 0.5f;
}

// -------------------------------------------------------------------------
// Kernel 0: deterministic cell sort.  One block per cell (4x4x4 grid over
// the 25^3 box).  Every block redundantly histograms all atoms' cells, takes
// its own base offset, then compacts its cell's atoms in ascending original
// index (ballot-prefix) -> fully deterministic ordering.
// -------------------------------------------------------------------------
__global__ __launch_bounds__(128) void cell_sort(
    const float* __restrict__ pos, int N)
{
    const int c    = blockIdx.x;          // my cell
    const int tid  = threadIdx.x;
    const int lane = tid & 31;
    const int w    = tid >> 5;

    __shared__ short scell[2048];
    __shared__ int   hist[64];
    __shared__ int   wc[4];
    __shared__ int   running, base;

    if (tid < 64) hist[tid] = 0;
    if (tid == 0) running = 0;
    __syncthreads();

    for (int j = tid; j < N; j += 128) {
        float x = pos[3 * j + 0];
        float y = pos[3 * j + 1];
        float z = pos[3 * j + 2];
        int cx = min(3, (int)(x * 0.16f));
        int cy = min(3, (int)(y * 0.16f));
        int cz = min(3, (int)(z * 0.16f));
        int cc = cx + 4 * cy + 16 * cz;
        scell[j] = (short)cc;
        atomicAdd(&hist[cc], 1);
    }
    __syncthreads();
    if (tid == 0) {
        int b = 0;
        for (int k = 0; k < c; k++) b += hist[k];
        base = b;
    }
    __syncthreads();

    for (int j0 = 0; j0 < N; j0 += 128) {
        int j = j0 + tid;
        int pred = (scell[j] == c);
        unsigned m = __ballot_sync(0xffffffffu, pred);
        if (lane == 0) wc[w] = __popc(m);
        __syncthreads();
        int off = 0;
        #pragma unroll
        for (int k = 0; k < 4; k++) if (k < w) off += wc[k];
        int tot = wc[0] + wc[1] + wc[2] + wc[3];
        if (pred) {
            int slot = base + running + off + __popc(m & ((1u << lane) - 1u));
            g_sperm[slot] = j;
            g_spos[3 * slot + 0] = pos[3 * j + 0];
            g_spos[3 * slot + 1] = pos[3 * j + 1];
            g_spos[3 * slot + 2] = pos[3 * j + 2];
        }
        __syncthreads();
        if (tid == 0) running += tot;
        __syncthreads();
    }
}

// -------------------------------------------------------------------------
// Kernel 1: descriptors in sorted space.  One WARP per (sorted atom, j-half),
// 8 warps/block.  Per 32-j chunk: bounding-sphere pretest (warp-uniform skip
// if min distance > rc), else ballot + compact survivor records into a
// warp-private smem slab, then uniform accumulate with broadcast LDS.
// Lane = (l, e): registers hold G[l,e] + M[l,p,e] (10 moments).
// -------------------------------------------------------------------------
__global__ __launch_bounds__(256) void feat_kernel(
    const float* __restrict__ spec,
    const float* __restrict__ kn_rad,
    const float* __restrict__ kn_ang,
    const float* __restrict__ rbf_w,
    const float* __restrict__ rbf_b,
    const float* __restrict__ rbf_aw,
    const float* __restrict__ rbf_ab,
    int N)
{
    const int tid  = threadIdx.x;
    const int wid  = tid >> 5;
    const int lane = tid & 31;
    const int g    = blockIdx.x * 8 + wid;
    const int s    = g >> 1;                 // sorted row (atom i)
    const int half = g & 1;
    const int myl  = lane >> 2;
    const int mye  = lane & 3;

    __shared__ float  spos[2048 * 3];        // 24 KB
    __shared__ float4 sbnd[64];              // center.xyz, (6+r)^2
    __shared__ float  rec[8][32 * 12];       // 12 KB warp slabs

    for (int idx = tid; idx < 3 * N; idx += 256) spos[idx] = g_spos[idx];
    __syncthreads();
    if (tid < 64) {
        float mnx = 1e9f, mny = 1e9f, mnz = 1e9f;
        float mxx = -1e9f, mxy = -1e9f, mxz = -1e9f;
        #pragma unroll 4
        for (int k = 0; k < 32; k++) {
            const float* p = &spos[(tid * 32 + k) * 3];
            mnx = fminf(mnx, p[0]); mxx = fmaxf(mxx, p[0]);
            mny = fminf(mny, p[1]); mxy = fmaxf(mxy, p[1]);
            mnz = fminf(mnz, p[2]); mxz = fmaxf(mxz, p[2]);
        }
        float cx = 0.5f * (mnx + mxx);
        float cy = 0.5f * (mny + mxy);
        float cz = 0.5f * (mnz + mxz);
        float r2 = 0.0f;
        #pragma unroll 4
        for (int k = 0; k < 32; k++) {
            const float* p = &spos[(tid * 32 + k) * 3];
            float dx = p[0] - cx, dy = p[1] - cy, dz = p[2] - cz;
            r2 = fmaxf(r2, fmaf(dx, dx, fmaf(dy, dy, dz * dz)));
        }
        float thr = 6.0f + sqrtf(r2);
        sbnd[tid] = make_float4(cx, cy, cz, thr * thr);
    }
    __syncthreads();

    const float crk = C6 * (float)(myl + 1) * kn_rad[myl];
    const float cak = C4 * (float)(myl + 1) * kn_ang[myl];
    const float wr = rbf_w[myl],  br = rbf_b[myl];
    const float wa = rbf_aw[myl], ba = rbf_ab[myl];

    const float pix = spos[3 * s + 0];
    const float piy = spos[3 * s + 1];
    const float piz = spos[3 * s + 2];
    const int   io  = g_sperm[s];
    const float4 si = __ldg(((const float4*)spec) + io);
    const float sie = (mye == 0) ? si.x : (mye == 1) ? si.y
                    : (mye == 2) ? si.z : si.w;

    float gacc = 0.0f;
    float macc[10];
    #pragma unroll
    for (int p = 0; p < 10; p++) macc[p] = 0.0f;

    float* slab = &rec[wid][0];
    const unsigned ltm = (1u << lane) - 1u;
    const int cbeg = half * (N >> 6);        // chunks of 32, halves of N/2
    const int cend = cbeg + (N >> 6);

    for (int c = cbeg; c < cend; c++) {
        float4 b = sbnd[c];
        float bdx = pix - b.x, bdy = piy - b.y, bdz = piz - b.z;
        if (fmaf(bdx, bdx, fmaf(bdy, bdy, bdz * bdz)) > b.w) continue;

        int j = c * 32 + lane;
        float rx = pix - spos[3 * j + 0];
        float ry = piy - spos[3 * j + 1];
        float rz = piz - spos[3 * j + 2];
        float d2 = fmaf(rx, rx, fmaf(ry, ry, rz * rz)) + 1e-16f;
        float inv = rsqrtf(d2);
        float rn = d2 * inv;
        bool pr = (j != s) && (rn <= 6.0f);
        bool pa = pr && (rn <= 4.0f);
        unsigned mr = __ballot_sync(0xffffffffu, pr);
        unsigned ma = __ballot_sync(0xffffffffu, pa);
        int cnt_a = __popc(ma);
        int cnt   = __popc(mr);
        if (!mr) continue;

        if (pr) {
            int slot = pa ? __popc(ma & ltm)
                          : cnt_a + __popc((mr & ~ma) & ltm);
            int jo = g_sperm[j];
            float4 sj = __ldg(((const float4*)spec) + jo);
            float* rp = slab + slot * 12;
            ((float4*)rp)[0] = make_float4(rx * inv, ry * inv, rz * inv, rn);
            ((float4*)rp)[1] = make_float4(inv, sj.x, sj.y, sj.z);
            rp[8] = sj.w;
        }
        __syncwarp();

        for (int q = 0; q < cnt_a; q++) {
            const float* rp = slab + q * 12;
            float4 u   = ((const float4*)rp)[0];
            float  riv = rp[4];
            float  spj = rp[5 + mye];
            float  srn = u.w;
            float fc   = 0.5f * (__cosf(C6 * srn) + 1.0f);
            float radl = __sinf(crk * srn) * (riv * fc)
                       * fast_sigmoid(fmaf(srn, wr, br));
            gacc = fmaf(radl, spj, gacc);

            float fca = 0.5f * (__cosf(C4 * srn) + 1.0f);
            float ral = __sinf(cak * srn) * (riv * fca)
                      * fast_sigmoid(fmaf(srn, wa, ba));
            float w  = ral * spj;
            float wx = w * u.x, wy = w * u.y, wz = w * u.z;
            macc[0] += w;
            macc[1] += wz;
            macc[2] += wy;
            macc[3] += wx;
            macc[4] = fmaf(wz, u.z, macc[4]);
            macc[5] = fmaf(wz, u.y, macc[5]);
            macc[6] = fmaf(wy, u.y, macc[6]);
            macc[7] = fmaf(wz, u.x, macc[7]);
            macc[8] = fmaf(wy, u.x, macc[8]);
            macc[9] = fmaf(wx, u.x, macc[9]);
        }
        for (int q = cnt_a; q < cnt; q++) {
            const float* rp = slab + q * 12;
            float srn = rp[3];
            float riv = rp[4];
            float spj = rp[5 + mye];
            float fc   = 0.5f * (__cosf(C6 * srn) + 1.0f);
            float radl = __sinf(crk * srn) * (riv * fc)
                       * fast_sigmoid(fmaf(srn, wr, br));
            gacc = fmaf(radl, spj, gacc);
        }
        __syncwarp();
    }

    float* fo = &g_feat[(half * 2048 + io) * NACC];
    fo[myl * 4 + mye] = gacc * sie;
    #pragma unroll
    for (int p = 0; p < 10; p++)
        fo[32 + myl * 40 + p * 4 + mye] = macc[p] * sie;
}

// -------------------------------------------------------------------------
// Kernel 2: fused MLP (672 -> 64 tanh -> 64 tanh -> 1).  8 atoms/block,
// 256 threads (h = tid&63, grp = tid>>6 owns atoms 2g, 2g+1).  Layer-1
// weights straight from L1/L2 (coalesced; unroll batches 16 LDGs), no
// inner barriers; layers 2-3 in-block.
// -------------------------------------------------------------------------
__global__ __launch_bounds__(256) void mlp_kernel(
    const float* __restrict__ W1, const float* __restrict__ b1,
    const float* __restrict__ W2, const float* __restrict__ b2,
    const float* __restrict__ W3, const float* __restrict__ b3,
    float* __restrict__ out, int N)
{
    const int i0   = blockIdx.x * 8;
    const int tid  = threadIdx.x;
    const int h    = tid & 63;
    const int grp  = tid >> 6;
    const int wid  = tid >> 5;

    __shared__ float sfr[NACC * 8];     // [f][a]  11 KB
    __shared__ float sh1[64 * 8];
    __shared__ float part[8][2];

    for (int idx = tid; idx < NACC * 8; idx += 256) {
        int aa = idx / NACC;
        int f  = idx - aa * NACC;
        sfr[f * 8 + aa] = g_feat[(i0 + aa) * NACC + f]
                        + g_feat[(2048 + i0 + aa) * NACC + f];
    }
    __syncthreads();

    float acc0 = 0.0f, acc1 = 0.0f;
    #pragma unroll 8
    for (int f = 0; f < 32; f++) {
        float w = __ldg(&W1[f * 64 + h]);
        float2 v = *(const float2*)&sfr[f * 8 + grp * 2];
        acc0 = fmaf(v.x, w, acc0);
        acc1 = fmaf(v.y, w, acc1);
    }
    #pragma unroll 8
    for (int f = 32; f < NACC; f++) {
        float w  = __ldg(&W1[f * 64 + h]);
        float ws = __ldg(&W1[(f + 320) * 64 + h]);
        float2 v = *(const float2*)&sfr[f * 8 + grp * 2];
        float t0 = fmaf(v.x, ws, w);
        float t1 = fmaf(v.y, ws, w);
        acc0 = fmaf(v.x, t0, acc0);
        acc1 = fmaf(v.y, t1, acc1);
    }
    {
        float bb = __ldg(&b1[h]);
        sh1[h * 8 + grp * 2 + 0] = fast_tanh(acc0 + bb);
        sh1[h * 8 + grp * 2 + 1] = fast_tanh(acc1 + bb);
    }
    __syncthreads();

    float bb = __ldg(&b2[h]);
    float s0 = bb, s1 = bb;
    #pragma unroll 8
    for (int k = 0; k < 64; k++) {
        float w = __ldg(&W2[k * 64 + h]);
        float2 v = *(const float2*)&sh1[k * 8 + grp * 2];
        s0 = fmaf(v.x, w, s0);
        s1 = fmaf(v.y, w, s1);
    }
    float w3 = __ldg(&W3[h]);
    float c0 = fast_tanh(s0) * w3;
    float c1 = fast_tanh(s1) * w3;
    #pragma unroll
    for (int o = 16; o > 0; o >>= 1) {
        c0 += __shfl_down_sync(0xffffffffu, c0, o);
        c1 += __shfl_down_sync(0xffffffffu, c1, o);
    }
    if ((tid & 31) == 0) { part[wid][0] = c0; part[wid][1] = c1; }
    __syncthreads();
    if (tid < 8) {
        int gg = tid >> 1, sub = tid & 1;
        out[i0 + tid] = part[2 * gg][sub] + part[2 * gg + 1][sub] + b3[0];
    }
}

// -------------------------------------------------------------------------
extern "C" void kernel_launch(void* const* d_in, const int* in_sizes, int n_in,
                              void* d_out, int out_size)
{
    const float* pos    = (const float*)d_in[0];
    const float* spec   = (const float*)d_in[1];
    const float* kn_rad = (const float*)d_in[2];
    const float* kn_ang = (const float*)d_in[3];
    const float* rbf_w  = (const float*)d_in[4];
    const float* rbf_b  = (const float*)d_in[5];
    const float* rbf_aw = (const float*)d_in[6];
    const float* rbf_ab = (const float*)d_in[7];
    const float* W1     = (const float*)d_in[8];
    const float* b1     = (const float*)d_in[9];
    const float* W2     = (const float*)d_in[10];
    const float* b2     = (const float*)d_in[11];
    const float* W3     = (const float*)d_in[12];
    const float* b3     = (const float*)d_in[13];

    int N = in_sizes[0] / 3;   // 2048

    cell_sort<<<64, 128>>>(pos, N);
    feat_kernel<<<2 * N / 8, 256>>>(spec, kn_rad, kn_ang,
                                    rbf_w, rbf_b, rbf_aw, rbf_ab, N);
    mlp_kernel<<<N / 8, 256>>>(W1, b1, W2, b2, W3, b3, (float*)d_out, N);
}